// round 1
// baseline (speedup 1.0000x reference)
#include <cuda_runtime.h>
#include <cuda_bf16.h>
#include <cstdint>

// ---------------- problem constants ----------------
#define BATCH 4
#define TT 16
#define HH_ 56
#define WW_ 56
#define CC 128
#define NHD 4
#define HD 32
#define NTOK (BATCH*TT*HH_*WW_)      // 200704
#define NWIN 2048                     // B * 512
#define NWTOK 98
#define LWIN 512
#define MREL 507
#define MLPH 512
#define SCALE 0.17677669529663687f    // 32^-0.5

// ---------------- scratch (device globals; no allocations allowed) ----------------
__device__ float g_win [(size_t)NTOK*CC];
__device__ float g_qkv [(size_t)NTOK*384];
__device__ float g_att [(size_t)NTOK*CC];
__device__ float g_proj[(size_t)NTOK*CC];
__device__ float g_xmid[(size_t)NTOK*CC];
__device__ float g_h   [(size_t)NTOK*CC];
__device__ float g_mlp [(size_t)NTOK*MLPH];

// ---------------- kernel 1: LN1 + cyclic shift + window partition ----------------
// warp per output window-token row; 4 warps per block
__global__ __launch_bounds__(128) void ln_shift_part_k(
    const float* __restrict__ x, const float* __restrict__ g,
    const float* __restrict__ b, float* __restrict__ win)
{
    int warp = threadIdx.x >> 5, lane = threadIdx.x & 31;
    int r = blockIdx.x * 4 + warp;           // window-token row, [0, NWIN*NWTOK)
    int w = r / NWTOK, n = r - w*NWTOK;
    int bb = w >> 9, l = w & 511;
    int tt = l >> 6, hh = (l >> 3) & 7, ww = l & 7;
    int wt = n / 49, rem = n - wt*49, wh = rem / 7, www = rem - wh*7;
    int tp = tt*2 + wt, hp = hh*7 + wh, wp = ww*7 + www;
    int ts = (tp + 1) & 15;                  // roll -1 on T
    int hs = hp + 3; if (hs >= 56) hs -= 56; // roll -3 on H
    int ws = wp + 3; if (ws >= 56) ws -= 56; // roll -3 on W
    size_t src = (((size_t)bb*TT + ts)*HH_ + hs)*WW_ + ws;

    float4 v = ((const float4*)(x + src*CC))[lane];
    float s  = v.x+v.y+v.z+v.w;
    float sq = v.x*v.x+v.y*v.y+v.z*v.z+v.w*v.w;
    #pragma unroll
    for (int o = 16; o; o >>= 1) {
        s  += __shfl_xor_sync(0xffffffffu, s,  o);
        sq += __shfl_xor_sync(0xffffffffu, sq, o);
    }
    float mu  = s * (1.f/128.f);
    float var = sq * (1.f/128.f) - mu*mu;
    float rstd = rsqrtf(var + 1e-5f);
    float4 gg = ((const float4*)g)[lane];
    float4 bv = ((const float4*)b)[lane];
    float4 o;
    o.x = (v.x-mu)*rstd*gg.x + bv.x;
    o.y = (v.y-mu)*rstd*gg.y + bv.y;
    o.z = (v.z-mu)*rstd*gg.z + bv.z;
    o.w = (v.w-mu)*rstd*gg.w + bv.w;
    ((float4*)(win + (size_t)r*CC))[lane] = o;
}

// ---------------- generic tiled GEMM: C = A[M,K] @ B[K,N] + bias, epilogues ----------------
// EPI 0: +bias   EPI 1: +bias then exact GELU   EPI 2: +bias +resid
#define BM 128
#define BN 64
#define BKK 16
#define ASTRIDE (BM + 4)

template<int EPI>
__global__ __launch_bounds__(256) void gemm_k(
    const float* __restrict__ A, const float* __restrict__ B,
    const float* __restrict__ bias, const float* __restrict__ resid,
    float* __restrict__ C, int M, int N, int K)
{
    __shared__ float As[BKK][ASTRIDE];
    __shared__ float Bs[BKK][BN];
    int tx = threadIdx.x & 15, ty = threadIdx.x >> 4;
    int m0 = blockIdx.y * BM, n0 = blockIdx.x * BN;
    int arow = threadIdx.x >> 2;          // 0..63
    int acol = (threadIdx.x & 3) * 4;     // 0,4,8,12
    int brow = threadIdx.x >> 4;          // 0..15
    int bcol = (threadIdx.x & 15) * 4;

    float acc[8][4];
    #pragma unroll
    for (int i=0;i<8;i++)
        #pragma unroll
        for (int j=0;j<4;j++) acc[i][j] = 0.f;

    for (int k0 = 0; k0 < K; k0 += BKK) {
        #pragma unroll
        for (int bb = 0; bb < 2; bb++) {
            float4 av = *(const float4*)&A[(size_t)(m0 + arow + 64*bb)*K + k0 + acol];
            As[acol+0][arow + 64*bb] = av.x;
            As[acol+1][arow + 64*bb] = av.y;
            As[acol+2][arow + 64*bb] = av.z;
            As[acol+3][arow + 64*bb] = av.w;
        }
        *(float4*)&Bs[brow][bcol] = *(const float4*)&B[(size_t)(k0 + brow)*N + n0 + bcol];
        __syncthreads();
        #pragma unroll
        for (int kk = 0; kk < BKK; kk++) {
            float bvr[4], avr[8];
            *(float4*)bvr    = *(float4*)&Bs[kk][tx*4];
            *(float4*)&avr[0]= *(float4*)&As[kk][ty*8];
            *(float4*)&avr[4]= *(float4*)&As[kk][ty*8+4];
            #pragma unroll
            for (int i=0;i<8;i++)
                #pragma unroll
                for (int j=0;j<4;j++)
                    acc[i][j] = fmaf(avr[i], bvr[j], acc[i][j]);
        }
        __syncthreads();
    }
    #pragma unroll
    for (int i=0;i<8;i++) {
        int row = m0 + ty*8 + i;
        #pragma unroll
        for (int j=0;j<4;j++) {
            int col = n0 + tx*4 + j;
            float c = acc[i][j] + bias[col];
            if (EPI == 1) c = 0.5f*c*(1.f + erff(c*0.70710678118654752f));
            if (EPI == 2) c += resid[(size_t)row*N + col];
            C[(size_t)row*N + col] = c;
        }
    }
}

// ---------------- kernel 3: attention per (window, head) ----------------
// dynamic smem: q[98*32] kT[32*100] v[98*32] sc[98*100] -> 77088 bytes
__global__ __launch_bounds__(128) void attn_k(
    const float* __restrict__ qkv, const float* __restrict__ rpe,
    const int* __restrict__ rpi, const float* __restrict__ mask,
    float* __restrict__ out)
{
    extern __shared__ float sm[];
    float* q  = sm;             // 3136
    float* kT = q + 3136;       // 3200 (stride 100)
    float* v  = kT + 3200;      // 3136
    float* sc = v + 3136;       // 9800 (stride 100)
    int w = blockIdx.x, h = blockIdx.y;
    int l = w & 511;
    int tid = threadIdx.x;
    const float* base = qkv + (size_t)w * NWTOK * 384;

    for (int i = tid; i < 3136; i += 128) {
        int n = i >> 5, d = i & 31;
        const float* p = base + (size_t)n*384 + h*HD + d;
        q[i]            = p[0] * SCALE;
        kT[d*100 + n]   = p[128];
        v[i]            = p[256];
    }
    __syncthreads();

    for (int i = tid; i < 9604; i += 128) {
        int n = i / 98, m = i - n*98;
        float s = 0.f;
        #pragma unroll
        for (int d = 0; d < 32; d++) s = fmaf(q[n*32+d], kT[d*100+m], s);
        s += rpe[h*MREL + rpi[i]] + mask[(size_t)l*9604 + i];
        sc[n*100 + m] = s;
    }
    __syncthreads();

    int warp = tid >> 5, lane = tid & 31;
    for (int n = warp; n < 98; n += 4) {
        float mx = -1e30f;
        for (int m = lane; m < 98; m += 32) mx = fmaxf(mx, sc[n*100+m]);
        #pragma unroll
        for (int o = 16; o; o >>= 1) mx = fmaxf(mx, __shfl_xor_sync(0xffffffffu, mx, o));
        float sum = 0.f;
        for (int m = lane; m < 98; m += 32) {
            float e = __expf(sc[n*100+m] - mx);
            sc[n*100+m] = e; sum += e;
        }
        #pragma unroll
        for (int o = 16; o; o >>= 1) sum += __shfl_xor_sync(0xffffffffu, sum, o);
        float inv = 1.f / sum;
        for (int m = lane; m < 98; m += 32) sc[n*100+m] *= inv;
    }
    __syncthreads();

    for (int i = tid; i < 3136; i += 128) {
        int n = i >> 5, d = i & 31;
        float s = 0.f;
        #pragma unroll 7
        for (int m = 0; m < 98; m++) s = fmaf(sc[n*100+m], v[m*32+d], s);
        out[(size_t)(w*NWTOK + n)*CC + h*HD + d] = s;
    }
}

// ---------------- kernel 5: un-partition + reverse shift + residual + LN2 ----------------
__global__ __launch_bounds__(128) void fuse_mid_k(
    const float* __restrict__ x, const float* __restrict__ proj,
    const float* __restrict__ g, const float* __restrict__ b,
    float* __restrict__ xmid, float* __restrict__ hout)
{
    int warp = threadIdx.x >> 5, lane = threadIdx.x & 31;
    int tok = blockIdx.x * 4 + warp;
    int q_ = tok;
    int w_ = q_ % 56; q_ /= 56;
    int h_ = q_ % 56; q_ /= 56;
    int t_ = q_ & 15; int bb = q_ >> 4;
    int tp = (t_ + 15) & 15;                 // roll +1 on T (inverse)
    int hp = h_ - 3; if (hp < 0) hp += 56;
    int wp = w_ - 3; if (wp < 0) wp += 56;
    int tt = tp >> 1, wt = tp & 1;
    int hh = hp / 7,  wh = hp - hh*7;
    int ww = wp / 7,  www = wp - ww*7;
    int widx = bb*LWIN + tt*64 + hh*8 + ww;
    int n = wt*49 + wh*7 + www;
    size_t prow = (size_t)widx*NWTOK + n;

    float4 xv = ((const float4*)(x    + (size_t)tok*CC))[lane];
    float4 pv = ((const float4*)(proj + prow*CC))[lane];
    float4 m; m.x = xv.x+pv.x; m.y = xv.y+pv.y; m.z = xv.z+pv.z; m.w = xv.w+pv.w;
    ((float4*)(xmid + (size_t)tok*CC))[lane] = m;

    float s  = m.x+m.y+m.z+m.w;
    float sq = m.x*m.x+m.y*m.y+m.z*m.z+m.w*m.w;
    #pragma unroll
    for (int o = 16; o; o >>= 1) {
        s  += __shfl_xor_sync(0xffffffffu, s,  o);
        sq += __shfl_xor_sync(0xffffffffu, sq, o);
    }
    float mu  = s * (1.f/128.f);
    float var = sq * (1.f/128.f) - mu*mu;
    float rstd = rsqrtf(var + 1e-5f);
    float4 gg = ((const float4*)g)[lane];
    float4 bv = ((const float4*)b)[lane];
    float4 o;
    o.x = (m.x-mu)*rstd*gg.x + bv.x;
    o.y = (m.y-mu)*rstd*gg.y + bv.y;
    o.z = (m.z-mu)*rstd*gg.z + bv.z;
    o.w = (m.w-mu)*rstd*gg.w + bv.w;
    ((float4*)(hout + (size_t)tok*CC))[lane] = o;
}

// ---------------- launch ----------------
extern "C" void kernel_launch(void* const* d_in, const int* in_sizes, int n_in,
                              void* d_out, int out_size)
{
    const float* x      = (const float*)d_in[0];
    const float* g1     = (const float*)d_in[1];
    const float* b1     = (const float*)d_in[2];
    const float* w_qkv  = (const float*)d_in[3];
    const float* b_qkv  = (const float*)d_in[4];
    const float* rpe    = (const float*)d_in[5];
    const float* w_proj = (const float*)d_in[6];
    const float* b_proj = (const float*)d_in[7];
    const float* g2     = (const float*)d_in[8];
    const float* b2     = (const float*)d_in[9];
    const float* w_fc1  = (const float*)d_in[10];
    const float* b_fc1  = (const float*)d_in[11];
    const float* w_fc2  = (const float*)d_in[12];
    const float* b_fc2  = (const float*)d_in[13];
    const float* mask   = (const float*)d_in[14];
    const int*   rpi    = (const int*)  d_in[15];

    float *win, *qkv, *att, *proj, *xmid, *hbuf, *mlp;
    cudaGetSymbolAddress((void**)&win , g_win);
    cudaGetSymbolAddress((void**)&qkv , g_qkv);
    cudaGetSymbolAddress((void**)&att , g_att);
    cudaGetSymbolAddress((void**)&proj, g_proj);
    cudaGetSymbolAddress((void**)&xmid, g_xmid);
    cudaGetSymbolAddress((void**)&hbuf, g_h);
    cudaGetSymbolAddress((void**)&mlp , g_mlp);

    const int ATTN_SMEM = (3136 + 3200 + 3136 + 9800) * 4;   // 77088 bytes
    cudaFuncSetAttribute(attn_k, cudaFuncAttributeMaxDynamicSharedMemorySize, ATTN_SMEM);

    // 1) LN1 + shift + partition
    ln_shift_part_k<<<NTOK/4, 128>>>(x, g1, b1, win);
    // 2) QKV GEMM [200704,128] @ [128,384]
    gemm_k<0><<<dim3(384/BN, NTOK/BM), 256>>>(win, w_qkv, b_qkv, nullptr, qkv, NTOK, 384, CC);
    // 3) attention per (window, head)
    attn_k<<<dim3(NWIN, NHD), 128, ATTN_SMEM>>>(qkv, rpe, rpi, mask, att);
    // 4) proj GEMM [200704,128] @ [128,128]
    gemm_k<0><<<dim3(CC/BN, NTOK/BM), 256>>>(att, w_proj, b_proj, nullptr, proj, NTOK, CC, CC);
    // 5) un-partition + reverse shift + residual + LN2
    fuse_mid_k<<<NTOK/4, 128>>>(x, proj, g2, b2, xmid, hbuf);
    // 6) fc1 + GELU [200704,128] @ [128,512]
    gemm_k<1><<<dim3(MLPH/BN, NTOK/BM), 256>>>(hbuf, w_fc1, b_fc1, nullptr, mlp, NTOK, MLPH, CC);
    // 7) fc2 + bias + residual -> out [200704,512] @ [512,128]
    gemm_k<2><<<dim3(CC/BN, NTOK/BM), 256>>>(mlp, w_fc2, b_fc2, xmid, (float*)d_out, NTOK, CC, MLPH);
}

// round 2
// speedup vs baseline: 1.5590x; 1.5590x over previous
#include <cuda_runtime.h>
#include <cuda_bf16.h>
#include <cstdint>

// ---------------- problem constants ----------------
#define BATCH 4
#define TT 16
#define HH_ 56
#define WW_ 56
#define CC 128
#define NHD 4
#define HD 32
#define NTOK (BATCH*TT*HH_*WW_)      // 200704
#define NWIN 2048
#define NWTOK 98
#define LWIN 512
#define MREL 507
#define MLPH 512
#define SCALE 0.17677669529663687f

// ---------------- scratch ----------------
__device__ float g_win [(size_t)NTOK*CC];
__device__ float g_qkv [(size_t)NTOK*384];
__device__ float g_att [(size_t)NTOK*CC];
__device__ float g_proj[(size_t)NTOK*CC];
__device__ float g_xmid[(size_t)NTOK*CC];
__device__ float g_h   [(size_t)NTOK*CC];
__device__ float g_mlp [(size_t)NTOK*MLPH];

__device__ __forceinline__ uint32_t f2tf32(float f) {
    uint32_t u; asm("cvt.rna.tf32.f32 %0, %1;" : "=r"(u) : "f"(f)); return u;
}

// ---------------- kernel 1: LN1 + cyclic shift + window partition ----------------
__global__ __launch_bounds__(128) void ln_shift_part_k(
    const float* __restrict__ x, const float* __restrict__ g,
    const float* __restrict__ b, float* __restrict__ win)
{
    int warp = threadIdx.x >> 5, lane = threadIdx.x & 31;
    int r = blockIdx.x * 4 + warp;
    int w = r / NWTOK, n = r - w*NWTOK;
    int bb = w >> 9, l = w & 511;
    int tt = l >> 6, hh = (l >> 3) & 7, ww = l & 7;
    int wt = n / 49, rem = n - wt*49, wh = rem / 7, www = rem - wh*7;
    int tp = tt*2 + wt, hp = hh*7 + wh, wp = ww*7 + www;
    int ts = (tp + 1) & 15;
    int hs = hp + 3; if (hs >= 56) hs -= 56;
    int ws = wp + 3; if (ws >= 56) ws -= 56;
    size_t src = (((size_t)bb*TT + ts)*HH_ + hs)*WW_ + ws;

    float4 v = ((const float4*)(x + src*CC))[lane];
    float s  = v.x+v.y+v.z+v.w;
    float sq = v.x*v.x+v.y*v.y+v.z*v.z+v.w*v.w;
    #pragma unroll
    for (int o = 16; o; o >>= 1) {
        s  += __shfl_xor_sync(0xffffffffu, s,  o);
        sq += __shfl_xor_sync(0xffffffffu, sq, o);
    }
    float mu  = s * (1.f/128.f);
    float var = sq * (1.f/128.f) - mu*mu;
    float rstd = rsqrtf(var + 1e-5f);
    float4 gg = ((const float4*)g)[lane];
    float4 bv = ((const float4*)b)[lane];
    float4 o;
    o.x = (v.x-mu)*rstd*gg.x + bv.x;
    o.y = (v.y-mu)*rstd*gg.y + bv.y;
    o.z = (v.z-mu)*rstd*gg.z + bv.z;
    o.w = (v.w-mu)*rstd*gg.w + bv.w;
    ((float4*)(win + (size_t)r*CC))[lane] = o;
}

// ---------------- tf32 tensor-core GEMM: C = A[M,K] @ B[K,N] + bias ----------------
// EPI 0: +bias   EPI 1: +bias,GELU   EPI 2: +bias,+resid
// 256 thr (8 warps), block tile 128x128x32, warp tile 64x32, mma m16n8k8
template<int EPI>
__global__ __launch_bounds__(256) void gemm_tc(
    const float* __restrict__ A, const float* __restrict__ B,
    const float* __restrict__ bias, const float* __restrict__ resid,
    float* __restrict__ C, int M, int N, int K)
{
    __shared__ uint32_t As[128][36];   // row-major [m][k], pad 36
    __shared__ uint32_t Bs[32][136];   // row-major [k][n], pad 136
    int tid = threadIdx.x, wid = tid >> 5, lane = tid & 31;
    int g = lane >> 2, tg = lane & 3;
    int m0 = blockIdx.y * 128, n0 = blockIdx.x * 128;
    int wm = (wid & 1) * 64, wn = (wid >> 1) * 32;

    float acc[4][4][4];
    #pragma unroll
    for (int i=0;i<4;i++)
        #pragma unroll
        for (int j=0;j<4;j++)
            #pragma unroll
            for (int r=0;r<4;r++) acc[i][j][r] = 0.f;

    int arow = tid >> 3, acol = (tid & 7) * 4;      // A: 4 rows/warp, coalesced
    int brow = tid >> 5, bcol = (tid & 31) * 4;     // B: coalesced

    for (int k0 = 0; k0 < K; k0 += 32) {
        #pragma unroll
        for (int rep = 0; rep < 4; rep++) {
            int row = rep*32 + arow;
            float4 av = *(const float4*)&A[(size_t)(m0 + row)*K + k0 + acol];
            uint4 u; u.x=f2tf32(av.x); u.y=f2tf32(av.y); u.z=f2tf32(av.z); u.w=f2tf32(av.w);
            *(uint4*)&As[row][acol] = u;
        }
        #pragma unroll
        for (int rep = 0; rep < 4; rep++) {
            int row = rep*8 + brow;
            float4 bv = *(const float4*)&B[(size_t)(k0 + row)*N + n0 + bcol];
            uint4 u; u.x=f2tf32(bv.x); u.y=f2tf32(bv.y); u.z=f2tf32(bv.z); u.w=f2tf32(bv.w);
            *(uint4*)&Bs[row][bcol] = u;
        }
        __syncthreads();
        #pragma unroll
        for (int kk = 0; kk < 4; kk++) {
            int kb = kk*8;
            uint32_t af[4][4], bf[4][2];
            #pragma unroll
            for (int mt = 0; mt < 4; mt++) {
                int mb = wm + mt*16;
                af[mt][0] = As[mb + g    ][kb + tg    ];
                af[mt][1] = As[mb + g + 8][kb + tg    ];
                af[mt][2] = As[mb + g    ][kb + tg + 4];
                af[mt][3] = As[mb + g + 8][kb + tg + 4];
            }
            #pragma unroll
            for (int nt = 0; nt < 4; nt++) {
                int nb = wn + nt*8;
                bf[nt][0] = Bs[kb + tg    ][nb + g];
                bf[nt][1] = Bs[kb + tg + 4][nb + g];
            }
            #pragma unroll
            for (int mt = 0; mt < 4; mt++)
                #pragma unroll
                for (int nt = 0; nt < 4; nt++)
                    asm volatile(
                        "mma.sync.aligned.m16n8k8.row.col.f32.tf32.tf32.f32 "
                        "{%0,%1,%2,%3}, {%4,%5,%6,%7}, {%8,%9}, {%0,%1,%2,%3};\n"
                        : "+f"(acc[mt][nt][0]), "+f"(acc[mt][nt][1]),
                          "+f"(acc[mt][nt][2]), "+f"(acc[mt][nt][3])
                        : "r"(af[mt][0]), "r"(af[mt][1]), "r"(af[mt][2]), "r"(af[mt][3]),
                          "r"(bf[nt][0]), "r"(bf[nt][1]));
        }
        __syncthreads();
    }

    #pragma unroll
    for (int mt = 0; mt < 4; mt++) {
        #pragma unroll
        for (int nt = 0; nt < 4; nt++) {
            int row = m0 + wm + mt*16 + g;
            int col = n0 + wn + nt*8 + tg*2;
            #pragma unroll
            for (int half = 0; half < 2; half++) {
                int rr = row + half*8;
                #pragma unroll
                for (int cc = 0; cc < 2; cc++) {
                    float c = acc[mt][nt][half*2 + cc] + bias[col + cc];
                    if (EPI == 1) c = 0.5f*c*(1.f + erff(c*0.70710678118654752f));
                    if (EPI == 2) c += resid[(size_t)rr*N + col + cc];
                    C[(size_t)rr*N + col + cc] = c;
                }
            }
        }
    }
}

// ---------------- kernel 3: attention per (window, head) ----------------
// smem: q[98*32], k[100*36], v[100*36], sc[98*100]  -> 80544 bytes
__global__ __launch_bounds__(128) void attn_k(
    const float* __restrict__ qkv, const float* __restrict__ rpe,
    const int* __restrict__ rpi, const float* __restrict__ mask,
    float* __restrict__ out)
{
    extern __shared__ float sm[];
    float* q  = sm;             // 3136
    float* k  = q + 3136;       // 3600 (stride 36)
    float* v  = k + 3600;       // 3600 (stride 36)
    float* sc = v + 3600;       // 9800 (stride 100)
    int w = blockIdx.x, h = blockIdx.y;
    int l = w & 511;
    int tid = threadIdx.x;
    const float* base = qkv + (size_t)w * NWTOK * 384;

    for (int i = tid; i < 3136; i += 128) {
        int n = i >> 5, d = i & 31;
        const float* p = base + (size_t)n*384 + h*HD + d;
        q[i]          = p[0] * SCALE;
        k[n*36 + d]   = p[128];
        v[n*36 + d]   = p[256];
    }
    if (tid < 72) { k[98*36 + tid] = 0.f; v[98*36 + tid] = 0.f; }
    __syncthreads();

    // scores: thread -> (n, m = b+25j, j=0..3), float4 over d
    for (int i = tid; i < 2450; i += 128) {
        int n = i / 25, b = i - n*25;
        const float4* q4 = (const float4*)(q + n*32);
        float s0=0.f, s1=0.f, s2=0.f, s3=0.f;
        #pragma unroll
        for (int dd = 0; dd < 8; dd++) {
            float4 qv = q4[dd];
            const float* kp = k + b*36 + dd*4;
            float4 k0v = *(const float4*)(kp);
            float4 k1v = *(const float4*)(kp + 25*36);
            float4 k2v = *(const float4*)(kp + 50*36);
            float4 k3v = *(const float4*)(kp + 75*36);
            s0 = fmaf(qv.x,k0v.x,fmaf(qv.y,k0v.y,fmaf(qv.z,k0v.z,fmaf(qv.w,k0v.w,s0))));
            s1 = fmaf(qv.x,k1v.x,fmaf(qv.y,k1v.y,fmaf(qv.z,k1v.z,fmaf(qv.w,k1v.w,s1))));
            s2 = fmaf(qv.x,k2v.x,fmaf(qv.y,k2v.y,fmaf(qv.z,k2v.z,fmaf(qv.w,k2v.w,s2))));
            s3 = fmaf(qv.x,k3v.x,fmaf(qv.y,k3v.y,fmaf(qv.z,k3v.z,fmaf(qv.w,k3v.w,s3))));
        }
        float sv[4] = {s0, s1, s2, s3};
        #pragma unroll
        for (int j = 0; j < 4; j++) {
            int m = b + 25*j;
            if (m < 98) {
                int nm = n*98 + m;
                sc[n*100 + m] = sv[j] + rpe[h*MREL + rpi[nm]] + mask[(size_t)l*9604 + nm];
            } else {
                sc[n*100 + m] = 0.f;
            }
        }
    }
    __syncthreads();

    int warp = tid >> 5, lane = tid & 31;
    for (int n = warp; n < 98; n += 4) {
        float mx = -1e30f;
        for (int m = lane; m < 98; m += 32) mx = fmaxf(mx, sc[n*100+m]);
        #pragma unroll
        for (int o = 16; o; o >>= 1) mx = fmaxf(mx, __shfl_xor_sync(0xffffffffu, mx, o));
        float sum = 0.f;
        for (int m = lane; m < 98; m += 32) {
            float e = __expf(sc[n*100+m] - mx);
            sc[n*100+m] = e; sum += e;
        }
        #pragma unroll
        for (int o = 16; o; o >>= 1) sum += __shfl_xor_sync(0xffffffffu, sum, o);
        float inv = 1.f / sum;
        for (int m = lane; m < 98; m += 32) sc[n*100+m] *= inv;
    }
    __syncthreads();

    // PV: thread -> (n, d4), float4 over d
    for (int i = tid; i < 784; i += 128) {
        int n = i >> 3, d4 = (i & 7) * 4;
        const float* srow = sc + n*100;
        float4 a = make_float4(0.f,0.f,0.f,0.f);
        #pragma unroll 2
        for (int m = 0; m < 98; m++) {
            float s = srow[m];
            float4 vv = *(const float4*)(v + m*36 + d4);
            a.x = fmaf(s, vv.x, a.x);
            a.y = fmaf(s, vv.y, a.y);
            a.z = fmaf(s, vv.z, a.z);
            a.w = fmaf(s, vv.w, a.w);
        }
        *(float4*)(out + (size_t)(w*NWTOK + n)*CC + h*HD + d4) = a;
    }
}

// ---------------- kernel 5: un-partition + reverse shift + residual + LN2 ----------------
__global__ __launch_bounds__(128) void fuse_mid_k(
    const float* __restrict__ x, const float* __restrict__ proj,
    const float* __restrict__ g, const float* __restrict__ b,
    float* __restrict__ xmid, float* __restrict__ hout)
{
    int warp = threadIdx.x >> 5, lane = threadIdx.x & 31;
    int tok = blockIdx.x * 4 + warp;
    int q_ = tok;
    int w_ = q_ % 56; q_ /= 56;
    int h_ = q_ % 56; q_ /= 56;
    int t_ = q_ & 15; int bb = q_ >> 4;
    int tp = (t_ + 15) & 15;
    int hp = h_ - 3; if (hp < 0) hp += 56;
    int wp = w_ - 3; if (wp < 0) wp += 56;
    int tt = tp >> 1, wt = tp & 1;
    int hh = hp / 7,  wh = hp - hh*7;
    int ww = wp / 7,  www = wp - ww*7;
    int widx = bb*LWIN + tt*64 + hh*8 + ww;
    int n = wt*49 + wh*7 + www;
    size_t prow = (size_t)widx*NWTOK + n;

    float4 xv = ((const float4*)(x    + (size_t)tok*CC))[lane];
    float4 pv = ((const float4*)(proj + prow*CC))[lane];
    float4 m; m.x = xv.x+pv.x; m.y = xv.y+pv.y; m.z = xv.z+pv.z; m.w = xv.w+pv.w;
    ((float4*)(xmid + (size_t)tok*CC))[lane] = m;

    float s  = m.x+m.y+m.z+m.w;
    float sq = m.x*m.x+m.y*m.y+m.z*m.z+m.w*m.w;
    #pragma unroll
    for (int o = 16; o; o >>= 1) {
        s  += __shfl_xor_sync(0xffffffffu, s,  o);
        sq += __shfl_xor_sync(0xffffffffu, sq, o);
    }
    float mu  = s * (1.f/128.f);
    float var = sq * (1.f/128.f) - mu*mu;
    float rstd = rsqrtf(var + 1e-5f);
    float4 gg = ((const float4*)g)[lane];
    float4 bv = ((const float4*)b)[lane];
    float4 o;
    o.x = (m.x-mu)*rstd*gg.x + bv.x;
    o.y = (m.y-mu)*rstd*gg.y + bv.y;
    o.z = (m.z-mu)*rstd*gg.z + bv.z;
    o.w = (m.w-mu)*rstd*gg.w + bv.w;
    ((float4*)(hout + (size_t)tok*CC))[lane] = o;
}

// ---------------- launch ----------------
extern "C" void kernel_launch(void* const* d_in, const int* in_sizes, int n_in,
                              void* d_out, int out_size)
{
    const float* x      = (const float*)d_in[0];
    const float* g1     = (const float*)d_in[1];
    const float* b1     = (const float*)d_in[2];
    const float* w_qkv  = (const float*)d_in[3];
    const float* b_qkv  = (const float*)d_in[4];
    const float* rpe    = (const float*)d_in[5];
    const float* w_proj = (const float*)d_in[6];
    const float* b_proj = (const float*)d_in[7];
    const float* g2     = (const float*)d_in[8];
    const float* b2     = (const float*)d_in[9];
    const float* w_fc1  = (const float*)d_in[10];
    const float* b_fc1  = (const float*)d_in[11];
    const float* w_fc2  = (const float*)d_in[12];
    const float* b_fc2  = (const float*)d_in[13];
    const float* mask   = (const float*)d_in[14];
    const int*   rpi    = (const int*)  d_in[15];

    float *win, *qkv, *att, *proj, *xmid, *hbuf, *mlp;
    cudaGetSymbolAddress((void**)&win , g_win);
    cudaGetSymbolAddress((void**)&qkv , g_qkv);
    cudaGetSymbolAddress((void**)&att , g_att);
    cudaGetSymbolAddress((void**)&proj, g_proj);
    cudaGetSymbolAddress((void**)&xmid, g_xmid);
    cudaGetSymbolAddress((void**)&hbuf, g_h);
    cudaGetSymbolAddress((void**)&mlp , g_mlp);

    const int ATTN_SMEM = (3136 + 3600 + 3600 + 9800) * 4;   // 80544 bytes
    cudaFuncSetAttribute(attn_k, cudaFuncAttributeMaxDynamicSharedMemorySize, ATTN_SMEM);

    ln_shift_part_k<<<NTOK/4, 128>>>(x, g1, b1, win);
    gemm_tc<0><<<dim3(384/128, NTOK/128), 256>>>(win, w_qkv, b_qkv, nullptr, qkv, NTOK, 384, CC);
    attn_k<<<dim3(NWIN, NHD), 128, ATTN_SMEM>>>(qkv, rpe, rpi, mask, att);
    gemm_tc<0><<<dim3(CC/128, NTOK/128), 256>>>(att, w_proj, b_proj, nullptr, proj, NTOK, CC, CC);
    fuse_mid_k<<<NTOK/4, 128>>>(x, proj, g2, b2, xmid, hbuf);
    gemm_tc<1><<<dim3(MLPH/128, NTOK/128), 256>>>(hbuf, w_fc1, b_fc1, nullptr, mlp, NTOK, MLPH, CC);
    gemm_tc<2><<<dim3(CC/128, NTOK/128), 256>>>(mlp, w_fc2, b_fc2, xmid, (float*)d_out, NTOK, CC, MLPH);
}

// round 3
// speedup vs baseline: 2.3091x; 1.4811x over previous
#include <cuda_runtime.h>
#include <cuda_bf16.h>
#include <cstdint>

// ---------------- problem constants ----------------
#define BATCH 4
#define TT 16
#define HH_ 56
#define WW_ 56
#define CC 128
#define NHD 4
#define HD 32
#define NTOK (BATCH*TT*HH_*WW_)      // 200704
#define NWIN 2048
#define NWTOK 98
#define LWIN 512
#define MREL 507
#define MLPH 512
#define SCALE 0.17677669529663687f

// ---------------- scratch ----------------
__device__ float g_win [(size_t)NTOK*CC];
__device__ float g_qkv [(size_t)NTOK*384];
__device__ float g_att [(size_t)NTOK*CC];
__device__ float g_proj[(size_t)NTOK*CC];
__device__ float g_xmid[(size_t)NTOK*CC];
__device__ float g_h   [(size_t)NTOK*CC];
__device__ float g_mlp [(size_t)NTOK*MLPH];

__device__ __forceinline__ uint32_t f2tf32(float f) {
    uint32_t u; asm("cvt.rna.tf32.f32 %0, %1;" : "=r"(u) : "f"(f)); return u;
}

// ---------------- kernel 1: LN1 + cyclic shift + window partition ----------------
__global__ __launch_bounds__(128) void ln_shift_part_k(
    const float* __restrict__ x, const float* __restrict__ g,
    const float* __restrict__ b, float* __restrict__ win)
{
    int warp = threadIdx.x >> 5, lane = threadIdx.x & 31;
    int r = blockIdx.x * 4 + warp;
    int w = r / NWTOK, n = r - w*NWTOK;
    int bb = w >> 9, l = w & 511;
    int tt = l >> 6, hh = (l >> 3) & 7, ww = l & 7;
    int wt = n / 49, rem = n - wt*49, wh = rem / 7, www = rem - wh*7;
    int tp = tt*2 + wt, hp = hh*7 + wh, wp = ww*7 + www;
    int ts = (tp + 1) & 15;
    int hs = hp + 3; if (hs >= 56) hs -= 56;
    int ws = wp + 3; if (ws >= 56) ws -= 56;
    size_t src = (((size_t)bb*TT + ts)*HH_ + hs)*WW_ + ws;

    float4 v = ((const float4*)(x + src*CC))[lane];
    float s  = v.x+v.y+v.z+v.w;
    float sq = v.x*v.x+v.y*v.y+v.z*v.z+v.w*v.w;
    #pragma unroll
    for (int o = 16; o; o >>= 1) {
        s  += __shfl_xor_sync(0xffffffffu, s,  o);
        sq += __shfl_xor_sync(0xffffffffu, sq, o);
    }
    float mu  = s * (1.f/128.f);
    float var = sq * (1.f/128.f) - mu*mu;
    float rstd = rsqrtf(var + 1e-5f);
    float4 gg = ((const float4*)g)[lane];
    float4 bv = ((const float4*)b)[lane];
    float4 o;
    o.x = (v.x-mu)*rstd*gg.x + bv.x;
    o.y = (v.y-mu)*rstd*gg.y + bv.y;
    o.z = (v.z-mu)*rstd*gg.z + bv.z;
    o.w = (v.w-mu)*rstd*gg.w + bv.w;
    ((float4*)(win + (size_t)r*CC))[lane] = o;
}

// ---------------- tf32 tensor-core GEMM ----------------
template<int EPI>
__global__ __launch_bounds__(256) void gemm_tc(
    const float* __restrict__ A, const float* __restrict__ B,
    const float* __restrict__ bias, const float* __restrict__ resid,
    float* __restrict__ C, int M, int N, int K)
{
    __shared__ uint32_t As[128][36];
    __shared__ uint32_t Bs[32][136];
    int tid = threadIdx.x, wid = tid >> 5, lane = tid & 31;
    int g = lane >> 2, tg = lane & 3;
    int m0 = blockIdx.y * 128, n0 = blockIdx.x * 128;
    int wm = (wid & 1) * 64, wn = (wid >> 1) * 32;

    float acc[4][4][4];
    #pragma unroll
    for (int i=0;i<4;i++)
        #pragma unroll
        for (int j=0;j<4;j++)
            #pragma unroll
            for (int r=0;r<4;r++) acc[i][j][r] = 0.f;

    int arow = tid >> 3, acol = (tid & 7) * 4;
    int brow = tid >> 5, bcol = (tid & 31) * 4;

    for (int k0 = 0; k0 < K; k0 += 32) {
        #pragma unroll
        for (int rep = 0; rep < 4; rep++) {
            int row = rep*32 + arow;
            float4 av = *(const float4*)&A[(size_t)(m0 + row)*K + k0 + acol];
            uint4 u; u.x=f2tf32(av.x); u.y=f2tf32(av.y); u.z=f2tf32(av.z); u.w=f2tf32(av.w);
            *(uint4*)&As[row][acol] = u;
        }
        #pragma unroll
        for (int rep = 0; rep < 4; rep++) {
            int row = rep*8 + brow;
            float4 bv = *(const float4*)&B[(size_t)(k0 + row)*N + n0 + bcol];
            uint4 u; u.x=f2tf32(bv.x); u.y=f2tf32(bv.y); u.z=f2tf32(bv.z); u.w=f2tf32(bv.w);
            *(uint4*)&Bs[row][bcol] = u;
        }
        __syncthreads();
        #pragma unroll
        for (int kk = 0; kk < 4; kk++) {
            int kb = kk*8;
            uint32_t af[4][4], bf[4][2];
            #pragma unroll
            for (int mt = 0; mt < 4; mt++) {
                int mb = wm + mt*16;
                af[mt][0] = As[mb + g    ][kb + tg    ];
                af[mt][1] = As[mb + g + 8][kb + tg    ];
                af[mt][2] = As[mb + g    ][kb + tg + 4];
                af[mt][3] = As[mb + g + 8][kb + tg + 4];
            }
            #pragma unroll
            for (int nt = 0; nt < 4; nt++) {
                int nb = wn + nt*8;
                bf[nt][0] = Bs[kb + tg    ][nb + g];
                bf[nt][1] = Bs[kb + tg + 4][nb + g];
            }
            #pragma unroll
            for (int mt = 0; mt < 4; mt++)
                #pragma unroll
                for (int nt = 0; nt < 4; nt++)
                    asm volatile(
                        "mma.sync.aligned.m16n8k8.row.col.f32.tf32.tf32.f32 "
                        "{%0,%1,%2,%3}, {%4,%5,%6,%7}, {%8,%9}, {%0,%1,%2,%3};\n"
                        : "+f"(acc[mt][nt][0]), "+f"(acc[mt][nt][1]),
                          "+f"(acc[mt][nt][2]), "+f"(acc[mt][nt][3])
                        : "r"(af[mt][0]), "r"(af[mt][1]), "r"(af[mt][2]), "r"(af[mt][3]),
                          "r"(bf[nt][0]), "r"(bf[nt][1]));
        }
        __syncthreads();
    }

    #pragma unroll
    for (int mt = 0; mt < 4; mt++) {
        #pragma unroll
        for (int nt = 0; nt < 4; nt++) {
            int row = m0 + wm + mt*16 + g;
            int col = n0 + wn + nt*8 + tg*2;
            #pragma unroll
            for (int half = 0; half < 2; half++) {
                int rr = row + half*8;
                #pragma unroll
                for (int cc = 0; cc < 2; cc++) {
                    float c = acc[mt][nt][half*2 + cc] + bias[col + cc];
                    if (EPI == 1) c = 0.5f*c*(1.f + erff(c*0.70710678118654752f));
                    if (EPI == 2) c += resid[(size_t)rr*N + col + cc];
                    C[(size_t)rr*N + col + cc] = c;
                }
            }
        }
    }
}

// ---------------- kernel 3: tensor-core attention per (window, head) ----------------
// smem (u32/float units): Qs[112*36]=4032, Ks[104*36]=3744, Vs[104*36]=3744,
//                         Ss[112*108]=12096  -> total 23616*4 = 94464 B
#define ATT_SM_U32 23616
__global__ __launch_bounds__(128) void attn_tc(
    const float* __restrict__ qkv, const float* __restrict__ rpe,
    const int* __restrict__ rpi, const float* __restrict__ mask,
    float* __restrict__ out)
{
    extern __shared__ uint32_t smu[];
    uint32_t* Qs = smu;                 // [112][36] tf32
    uint32_t* Ks = smu + 4032;          // [104][36] tf32 (token-major)
    uint32_t* Vs = smu + 7776;          // [104][36] tf32 (token-major)
    float*    Ss = (float*)(smu + 11520); // [112][108]

    int w = blockIdx.x, h = blockIdx.y;
    int l = w & 511;
    int tid = threadIdx.x, warp = tid >> 5, lane = tid & 31;
    int g = lane >> 2, tg = lane & 3;
    const float* base = qkv + (size_t)w * NWTOK * 384 + h*HD;

    // load Q,K,V -> tf32 smem
    for (int i = tid; i < 3136; i += 128) {
        int n = i >> 5, d = i & 31;
        const float* p = base + (size_t)n*384 + d;
        Qs[n*36 + d] = f2tf32(p[0] * SCALE);
        Ks[n*36 + d] = f2tf32(p[128]);
        Vs[n*36 + d] = f2tf32(p[256]);
    }
    // zero pad token rows 98..103 of K and V
    for (int i = tid; i < 216; i += 128) {
        Ks[3528 + i] = 0;   // 98*36 = 3528
        Vs[3528 + i] = 0;
    }
    __syncthreads();

    // S = Q @ K^T : M=112 (7 m-tiles), N=104 (13 n-tiles), K=32 (4 k-steps)
    for (int mt = warp; mt < 7; mt += 4) {
        float acc[13][4];
        #pragma unroll
        for (int nt = 0; nt < 13; nt++)
            #pragma unroll
            for (int r = 0; r < 4; r++) acc[nt][r] = 0.f;
        #pragma unroll
        for (int kk = 0; kk < 4; kk++) {
            int kb = kk*8;
            int mb = mt*16;
            uint32_t a0 = Qs[(mb + g    )*36 + kb + tg    ];
            uint32_t a1 = Qs[(mb + g + 8)*36 + kb + tg    ];
            uint32_t a2 = Qs[(mb + g    )*36 + kb + tg + 4];
            uint32_t a3 = Qs[(mb + g + 8)*36 + kb + tg + 4];
            #pragma unroll
            for (int nt = 0; nt < 13; nt++) {
                uint32_t b0 = Ks[(nt*8 + g)*36 + kb + tg    ];
                uint32_t b1 = Ks[(nt*8 + g)*36 + kb + tg + 4];
                asm volatile(
                    "mma.sync.aligned.m16n8k8.row.col.f32.tf32.tf32.f32 "
                    "{%0,%1,%2,%3}, {%4,%5,%6,%7}, {%8,%9}, {%0,%1,%2,%3};\n"
                    : "+f"(acc[nt][0]), "+f"(acc[nt][1]), "+f"(acc[nt][2]), "+f"(acc[nt][3])
                    : "r"(a0), "r"(a1), "r"(a2), "r"(a3), "r"(b0), "r"(b1));
            }
        }
        #pragma unroll
        for (int nt = 0; nt < 13; nt++) {
            int col = nt*8 + tg*2;
            *(float2*)&Ss[(mt*16 + g    )*108 + col] = make_float2(acc[nt][0], acc[nt][1]);
            *(float2*)&Ss[(mt*16 + g + 8)*108 + col] = make_float2(acc[nt][2], acc[nt][3]);
        }
    }
    __syncthreads();

    // softmax rows (bias fused here)
    {
        const float* mrow = mask + (size_t)l*9604;
        const float* rp = rpe + h*MREL;
        for (int n = warp; n < 98; n += 4) {
            float* row = Ss + n*108;
            int nb = n*98;
            float s0 = row[lane]    + rp[rpi[nb+lane]]    + mrow[nb+lane];
            float s1 = row[lane+32] + rp[rpi[nb+lane+32]] + mrow[nb+lane+32];
            float s2 = row[lane+64] + rp[rpi[nb+lane+64]] + mrow[nb+lane+64];
            float s3 = (lane < 2) ? row[lane+96] + rp[rpi[nb+lane+96]] + mrow[nb+lane+96]
                                  : -1e30f;
            float mx = fmaxf(fmaxf(s0,s1), fmaxf(s2,s3));
            #pragma unroll
            for (int o = 16; o; o >>= 1) mx = fmaxf(mx, __shfl_xor_sync(0xffffffffu, mx, o));
            float e0 = __expf(s0-mx), e1 = __expf(s1-mx), e2 = __expf(s2-mx);
            float e3 = (lane < 2) ? __expf(s3-mx) : 0.f;
            float sum = e0+e1+e2+e3;
            #pragma unroll
            for (int o = 16; o; o >>= 1) sum += __shfl_xor_sync(0xffffffffu, sum, o);
            float inv = 1.f / sum;
            row[lane]    = e0*inv;
            row[lane+32] = e1*inv;
            row[lane+64] = e2*inv;
            if (lane < 2) row[lane+96] = e3*inv;
            if (lane < 6) row[98+lane] = 0.f;   // zero pad cols 98..103
        }
    }
    __syncthreads();

    // O = P @ V : M=112 (7 m-tiles), N=32 (4 n-tiles), K=104 (13 k-steps)
    for (int mt = warp; mt < 7; mt += 4) {
        float acc[4][4];
        #pragma unroll
        for (int nt = 0; nt < 4; nt++)
            #pragma unroll
            for (int r = 0; r < 4; r++) acc[nt][r] = 0.f;
        int mb = mt*16;
        #pragma unroll
        for (int kk = 0; kk < 13; kk++) {
            int kb = kk*8;
            uint32_t a0 = f2tf32(Ss[(mb + g    )*108 + kb + tg    ]);
            uint32_t a1 = f2tf32(Ss[(mb + g + 8)*108 + kb + tg    ]);
            uint32_t a2 = f2tf32(Ss[(mb + g    )*108 + kb + tg + 4]);
            uint32_t a3 = f2tf32(Ss[(mb + g + 8)*108 + kb + tg + 4]);
            #pragma unroll
            for (int nt = 0; nt < 4; nt++) {
                uint32_t b0 = Vs[(kb + tg    )*36 + nt*8 + g];
                uint32_t b1 = Vs[(kb + tg + 4)*36 + nt*8 + g];
                asm volatile(
                    "mma.sync.aligned.m16n8k8.row.col.f32.tf32.tf32.f32 "
                    "{%0,%1,%2,%3}, {%4,%5,%6,%7}, {%8,%9}, {%0,%1,%2,%3};\n"
                    : "+f"(acc[nt][0]), "+f"(acc[nt][1]), "+f"(acc[nt][2]), "+f"(acc[nt][3])
                    : "r"(a0), "r"(a1), "r"(a2), "r"(a3), "r"(b0), "r"(b1));
            }
        }
        #pragma unroll
        for (int nt = 0; nt < 4; nt++) {
            int col = h*HD + nt*8 + tg*2;
            int r0 = mb + g, r1 = mb + g + 8;
            if (r0 < 98)
                *(float2*)&out[(size_t)(w*NWTOK + r0)*CC + col] = make_float2(acc[nt][0], acc[nt][1]);
            if (r1 < 98)
                *(float2*)&out[(size_t)(w*NWTOK + r1)*CC + col] = make_float2(acc[nt][2], acc[nt][3]);
        }
    }
}

// ---------------- kernel 5: un-partition + reverse shift + residual + LN2 ----------------
__global__ __launch_bounds__(128) void fuse_mid_k(
    const float* __restrict__ x, const float* __restrict__ proj,
    const float* __restrict__ g, const float* __restrict__ b,
    float* __restrict__ xmid, float* __restrict__ hout)
{
    int warp = threadIdx.x >> 5, lane = threadIdx.x & 31;
    int tok = blockIdx.x * 4 + warp;
    int q_ = tok;
    int w_ = q_ % 56; q_ /= 56;
    int h_ = q_ % 56; q_ /= 56;
    int t_ = q_ & 15; int bb = q_ >> 4;
    int tp = (t_ + 15) & 15;
    int hp = h_ - 3; if (hp < 0) hp += 56;
    int wp = w_ - 3; if (wp < 0) wp += 56;
    int tt = tp >> 1, wt = tp & 1;
    int hh = hp / 7,  wh = hp - hh*7;
    int ww = wp / 7,  www = wp - ww*7;
    int widx = bb*LWIN + tt*64 + hh*8 + ww;
    int n = wt*49 + wh*7 + www;
    size_t prow = (size_t)widx*NWTOK + n;

    float4 xv = ((const float4*)(x    + (size_t)tok*CC))[lane];
    float4 pv = ((const float4*)(proj + prow*CC))[lane];
    float4 m; m.x = xv.x+pv.x; m.y = xv.y+pv.y; m.z = xv.z+pv.z; m.w = xv.w+pv.w;
    ((float4*)(xmid + (size_t)tok*CC))[lane] = m;

    float s  = m.x+m.y+m.z+m.w;
    float sq = m.x*m.x+m.y*m.y+m.z*m.z+m.w*m.w;
    #pragma unroll
    for (int o = 16; o; o >>= 1) {
        s  += __shfl_xor_sync(0xffffffffu, s,  o);
        sq += __shfl_xor_sync(0xffffffffu, sq, o);
    }
    float mu  = s * (1.f/128.f);
    float var = sq * (1.f/128.f) - mu*mu;
    float rstd = rsqrtf(var + 1e-5f);
    float4 gg = ((const float4*)g)[lane];
    float4 bv = ((const float4*)b)[lane];
    float4 o;
    o.x = (m.x-mu)*rstd*gg.x + bv.x;
    o.y = (m.y-mu)*rstd*gg.y + bv.y;
    o.z = (m.z-mu)*rstd*gg.z + bv.z;
    o.w = (m.w-mu)*rstd*gg.w + bv.w;
    ((float4*)(hout + (size_t)tok*CC))[lane] = o;
}

// ---------------- launch ----------------
extern "C" void kernel_launch(void* const* d_in, const int* in_sizes, int n_in,
                              void* d_out, int out_size)
{
    const float* x      = (const float*)d_in[0];
    const float* g1     = (const float*)d_in[1];
    const float* b1     = (const float*)d_in[2];
    const float* w_qkv  = (const float*)d_in[3];
    const float* b_qkv  = (const float*)d_in[4];
    const float* rpe    = (const float*)d_in[5];
    const float* w_proj = (const float*)d_in[6];
    const float* b_proj = (const float*)d_in[7];
    const float* g2     = (const float*)d_in[8];
    const float* b2     = (const float*)d_in[9];
    const float* w_fc1  = (const float*)d_in[10];
    const float* b_fc1  = (const float*)d_in[11];
    const float* w_fc2  = (const float*)d_in[12];
    const float* b_fc2  = (const float*)d_in[13];
    const float* mask   = (const float*)d_in[14];
    const int*   rpi    = (const int*)  d_in[15];

    float *win, *qkv, *att, *proj, *xmid, *hbuf, *mlp;
    cudaGetSymbolAddress((void**)&win , g_win);
    cudaGetSymbolAddress((void**)&qkv , g_qkv);
    cudaGetSymbolAddress((void**)&att , g_att);
    cudaGetSymbolAddress((void**)&proj, g_proj);
    cudaGetSymbolAddress((void**)&xmid, g_xmid);
    cudaGetSymbolAddress((void**)&hbuf, g_h);
    cudaGetSymbolAddress((void**)&mlp , g_mlp);

    const int ATTN_SMEM = ATT_SM_U32 * 4;   // 94464 bytes
    cudaFuncSetAttribute(attn_tc, cudaFuncAttributeMaxDynamicSharedMemorySize, ATTN_SMEM);

    ln_shift_part_k<<<NTOK/4, 128>>>(x, g1, b1, win);
    gemm_tc<0><<<dim3(384/128, NTOK/128), 256>>>(win, w_qkv, b_qkv, nullptr, qkv, NTOK, 384, CC);
    attn_tc<<<dim3(NWIN, NHD), 128, ATTN_SMEM>>>(qkv, rpe, rpi, mask, att);
    gemm_tc<0><<<dim3(CC/128, NTOK/128), 256>>>(att, w_proj, b_proj, nullptr, proj, NTOK, CC, CC);
    fuse_mid_k<<<NTOK/4, 128>>>(x, proj, g2, b2, xmid, hbuf);
    gemm_tc<1><<<dim3(MLPH/128, NTOK/128), 256>>>(hbuf, w_fc1, b_fc1, nullptr, mlp, NTOK, MLPH, CC);
    gemm_tc<2><<<dim3(CC/128, NTOK/128), 256>>>(mlp, w_fc2, b_fc2, xmid, (float*)d_out, NTOK, CC, MLPH);
}